// round 16
// baseline (speedup 1.0000x reference)
#include <cuda_runtime.h>
#include <cuda_bf16.h>
#include <math.h>
#include <stdint.h>

#define MAXN 100000
#define MAXE 1600000
#define MAXET (MAXN + MAXE)

#define NEG_ATT 0.2f
#define NEG_ACT 0.01f

// ---------------- scratch ----------------
__device__ float g_h1f[MAXN * 128];   // layer-1 features, fp32 (FFMA2-direct)
__device__ float g_as1[MAXN * 8];
__device__ float g_ad1[MAXN * 8];
__device__ float g_h2[MAXN * 16];
__device__ float g_as2[MAXN];
__device__ float g_ad2[MAXN];
__device__ int   g_deg[MAXN];
__device__ int   g_rs[MAXN + 1];
__device__ int   g_cur[MAXN];
__device__ int   g_esrc[MAXET];
__device__ volatile int g_flag[256];
__device__ int g_aggval[256];
__device__ int g_prefval[256];
__device__ int g_done;

__global__ void k_nop() {}

// ---------------- f32x2 helpers ----------------
__device__ __forceinline__ unsigned long long ffma2(unsigned long long a,
                                                    unsigned long long b,
                                                    unsigned long long c) {
    unsigned long long d;
    asm("fma.rn.f32x2 %0, %1, %2, %3;" : "=l"(d) : "l"(a), "l"(b), "l"(c));
    return d;
}
__device__ __forceinline__ unsigned long long pack2(float a, float b) {
    unsigned long long r;
    asm("mov.b64 %0, {%1, %2};" : "=l"(r) : "f"(a), "f"(b));
    return r;
}
__device__ __forceinline__ float2 unpack2(unsigned long long v) {
    float2 r;
    asm("mov.b64 {%0, %1}, %2;" : "=f"(r.x), "=f"(r.y) : "l"(v));
    return r;
}

// -------- fat kernel: SGEMM1 (128x128x128, 8x8 microtile, FFMA2) + alpha1 || hist --------
#define HIST_B 256
__global__ void __launch_bounds__(256, 2) k_fat(const float* __restrict__ x,
                      const float* __restrict__ W,
                      const float* __restrict__ a1s, const float* __restrict__ a1d,
                      const int* __restrict__ dst, int N, int E, int GB) {
    if (blockIdx.x == 0 && threadIdx.x == 0) g_done = 0;
    if (blockIdx.x >= GB) {
        int b = blockIdx.x - GB;
        for (int e = b * 256 + threadIdx.x; e < E; e += 256 * HIST_B)
            atomicAdd(&g_deg[dst[e]], 1);
        return;
    }
    __shared__ float As[16][128];   // k-major: As[k][node]
    __shared__ float Bs[16][128];   // Bs[k][col]
    int t = threadIdx.x;
    int tx = t & 15;
    int ty = t >> 4;
    int n0 = blockIdx.x * 128;
    const float4* x4 = (const float4*)x;
    const float4* W4 = (const float4*)W;

    unsigned long long acc[8][4];
#pragma unroll
    for (int i = 0; i < 8; i++)
#pragma unroll
        for (int j = 0; j < 4; j++) acc[i][j] = 0ULL;

    for (int kc = 0; kc < 128; kc += 16) {
#pragma unroll
        for (int i = 0; i < 2; i++) {
            int s = t * 2 + i;
            int row = s >> 2, c4 = s & 3;
            float4 v = make_float4(0.f, 0.f, 0.f, 0.f);
            if (n0 + row < N) v = x4[(size_t)(n0 + row) * 32 + (kc >> 2) + c4];
            As[c4 * 4 + 0][row] = v.x;
            As[c4 * 4 + 1][row] = v.y;
            As[c4 * 4 + 2][row] = v.z;
            As[c4 * 4 + 3][row] = v.w;
        }
#pragma unroll
        for (int i = 0; i < 2; i++) {
            int s = t * 2 + i;
            int row = s >> 5, c4 = s & 31;
            ((float4*)Bs[row])[c4] = W4[(size_t)(kc + row) * 32 + c4];
        }
        __syncthreads();
#pragma unroll
        for (int kk = 0; kk < 16; kk++) {
            float4 af0 = *(const float4*)&As[kk][ty * 8];
            float4 af1 = *(const float4*)&As[kk][ty * 8 + 4];
            const unsigned long long* bp = (const unsigned long long*)&Bs[kk][tx * 8];
            unsigned long long b0 = bp[0], b1 = bp[1], b2 = bp[2], b3 = bp[3];
            float a[8] = {af0.x, af0.y, af0.z, af0.w, af1.x, af1.y, af1.z, af1.w};
#pragma unroll
            for (int i = 0; i < 8; i++) {
                unsigned long long aa = pack2(a[i], a[i]);
                acc[i][0] = ffma2(aa, b0, acc[i][0]);
                acc[i][1] = ffma2(aa, b1, acc[i][1]);
                acc[i][2] = ffma2(aa, b2, acc[i][2]);
                acc[i][3] = ffma2(aa, b3, acc[i][3]);
            }
        }
        __syncthreads();
    }

    float asv[8], adv[8];
#pragma unroll
    for (int j = 0; j < 8; j++) {
        asv[j] = __ldg(&a1s[tx * 8 + j]);
        adv[j] = __ldg(&a1d[tx * 8 + j]);
    }
    int hh = tx >> 1;
#pragma unroll
    for (int i = 0; i < 8; i++) {
        int n = n0 + ty * 8 + i;
        float h[8];
#pragma unroll
        for (int j = 0; j < 4; j++) {
            float2 p = unpack2(acc[i][j]);
            h[2 * j] = p.x;
            h[2 * j + 1] = p.y;
        }
        float vs = 0.f, vd = 0.f;
#pragma unroll
        for (int j = 0; j < 8; j++) {
            vs = fmaf(h[j], asv[j], vs);
            vd = fmaf(h[j], adv[j], vd);
        }
        vs += __shfl_xor_sync(0xFFFFFFFFu, vs, 1);
        vd += __shfl_xor_sync(0xFFFFFFFFu, vd, 1);
        if (n < N) {
            float* dstp = g_h1f + (size_t)n * 128 + tx * 8;
            *(float4*)(dstp + 0) = make_float4(h[0], h[1], h[2], h[3]);
            *(float4*)(dstp + 4) = make_float4(h[4], h[5], h[6], h[7]);
            if ((tx & 1) == 0) {
                g_as1[n * 8 + hh] = vs;
                g_ad1[n * 8 + hh] = vd;
            }
        }
    }
}

// ------- CSR offsets (decoupled lookback) + edge scatter, fused via phase barrier -------
__global__ void __launch_bounds__(512) k_csrsc(const int* __restrict__ src,
                                               const int* __restrict__ dst,
                                               int N, int E, int nb) {
    __shared__ int s[512];
    __shared__ int s_excl;
    int t = threadIdx.x;
    int b = blockIdx.x;
    int i = b * 512 + t;
    int v = (i < N) ? g_deg[i] + 1 : 0;
    s[t] = v;
    __syncthreads();
    for (int off = 1; off < 512; off <<= 1) {
        int x = (t >= off) ? s[t - off] : 0;
        __syncthreads();
        s[t] += x;
        __syncthreads();
    }
    int incl = s[t];
    int total = s[511];

    if (t < 32) {
        if (b == 0) {
            if (t == 0) {
                g_prefval[0] = total;
                __threadfence();
                g_flag[0] = 2;
                s_excl = 0;
                if (nb == 1) g_rs[N] = total;
            }
        } else {
            if (t == 0) {
                g_aggval[b] = total;
                __threadfence();
                g_flag[b] = 1;
            }
            __syncwarp();
            int run = 0;
            int hi = b;
            while (true) {
                int p = hi - 32 + t;
                int f = 2, val = 0;
                if (p >= 0) {
                    do { f = g_flag[p]; } while (f == 0);
                    val = (f == 2) ? g_prefval[p] : g_aggval[p];
                }
                unsigned m = __ballot_sync(0xFFFFFFFFu, f == 2);
                if (m) {
                    int lead = 31 - __clz(m);
                    int contrib = (t >= lead) ? val : 0;
                    run += __reduce_add_sync(0xFFFFFFFFu, contrib);
                    break;
                } else {
                    run += __reduce_add_sync(0xFFFFFFFFu, val);
                    hi -= 32;
                }
            }
            if (t == 0) {
                g_prefval[b] = run + total;
                __threadfence();
                g_flag[b] = 2;
                s_excl = run;
                if (b == nb - 1) g_rs[N] = run + total;
            }
        }
    }
    __syncthreads();
    int excl = s_excl + incl - v;
    if (i < N) {
        g_rs[i] = excl;
        g_cur[i] = excl + 1;
        g_esrc[excl] = i;
        g_deg[i] = 0;
    }

    __threadfence();
    __syncthreads();
    if (t == 0) {
        atomicAdd(&g_done, 1);
        while (*(volatile int*)&g_done < nb) { }
    }
    __syncthreads();
    __threadfence();

    if (b == 0 && t < 256) g_flag[t] = 0;
    int gtid = b * 512 + t;
    int nthreads = nb * 512;
    int E4 = E >> 2;
    for (int q = gtid; q < E4; q += nthreads) {
        int4 s4 = *(const int4*)(src + q * 4);
        int4 d4 = *(const int4*)(dst + q * 4);
        int p0 = atomicAdd(&g_cur[d4.x], 1);
        int p1 = atomicAdd(&g_cur[d4.y], 1);
        int p2 = atomicAdd(&g_cur[d4.z], 1);
        int p3 = atomicAdd(&g_cur[d4.w], 1);
        g_esrc[p0] = s4.x;
        g_esrc[p1] = s4.y;
        g_esrc[p2] = s4.z;
        g_esrc[p3] = s4.w;
    }
    if (gtid == 0) {
        for (int e = E4 * 4; e < E; e++) {
            int p = atomicAdd(&g_cur[dst[e]], 1);
            g_esrc[p] = src[e];
        }
    }
}

// ------- layer-1 gather: 2 edges/warp, fp32 rows -> direct FFMA2 + fused GEMM2 -------
__global__ void __launch_bounds__(256) k_gather1(const float* __restrict__ b1,
                                                 const float* __restrict__ W2,
                                                 const float* __restrict__ a2s,
                                                 const float* __restrict__ a2d,
                                                 int N) {
    __shared__ float W2s[128 * 16];
    __shared__ float hbs[8][132];
    int t = threadIdx.x;
    for (int i = t; i < 2048; i += 256) W2s[i] = W2[i];
    __syncthreads();

    int wib = t >> 5;
    int warp = blockIdx.x * 8 + wib;
    if (warp >= N) return;
    int n = warp;
    int l = t & 31;
    int half = l >> 4;        // which edge of the pair
    int li = l & 15;          // owns floats 8*li..8*li+7
    int h = li >> 1;          // head
    int beg = g_rs[n];
    int end = g_rs[n + 1];
    float adh = g_ad1[n * 8 + h];

    const ulonglong2* h1p = (const ulonglong2*)g_h1f;  // row = 32 ulonglong2 (128 f32)
    unsigned long long acc64[4];
#pragma unroll
    for (int k = 0; k < 4; k++) acc64[k] = 0ULL;
    float ds = 0.f;

    int i = beg;
    int p0 = 0, p1 = 0;
    if (i + 4 <= end) {
        p0 = g_esrc[i + half];
        p1 = g_esrc[i + 2 + half];
    }
    while (i + 4 <= end) {
        int s0 = p0, s1 = p1;
        int inext = i + 4;
        if (inext + 4 <= end) {
            p0 = g_esrc[inext + half];
            p1 = g_esrc[inext + 2 + half];
        }
        float a0 = g_as1[s0 * 8 + h];
        float a1 = g_as1[s1 * 8 + h];
        ulonglong2 v00 = h1p[(size_t)s0 * 32 + 2 * li];
        ulonglong2 v01 = h1p[(size_t)s0 * 32 + 2 * li + 1];
        ulonglong2 v10 = h1p[(size_t)s1 * 32 + 2 * li];
        ulonglong2 v11 = h1p[(size_t)s1 * 32 + 2 * li + 1];
        float e0 = a0 + adh; e0 = fmaxf(e0, NEG_ATT * e0);
        float e1 = a1 + adh; e1 = fmaxf(e1, NEG_ATT * e1);
        float x0 = __expf(e0), x1 = __expf(e1);
        ds += x0 + x1;
        unsigned long long xx0 = pack2(x0, x0);
        unsigned long long xx1 = pack2(x1, x1);
        acc64[0] = ffma2(v00.x, xx0, acc64[0]);
        acc64[1] = ffma2(v00.y, xx0, acc64[1]);
        acc64[2] = ffma2(v01.x, xx0, acc64[2]);
        acc64[3] = ffma2(v01.y, xx0, acc64[3]);
        acc64[0] = ffma2(v10.x, xx1, acc64[0]);
        acc64[1] = ffma2(v10.y, xx1, acc64[1]);
        acc64[2] = ffma2(v11.x, xx1, acc64[2]);
        acc64[3] = ffma2(v11.y, xx1, acc64[3]);
        i = inext;
    }
    // tail (0..3 edges): half0 covers i, i+2; half1 covers i+1
    if (i + half < end) {
        int s = g_esrc[i + half];
        float a = g_as1[s * 8 + h];
        ulonglong2 v0 = h1p[(size_t)s * 32 + 2 * li];
        ulonglong2 v1 = h1p[(size_t)s * 32 + 2 * li + 1];
        float e = a + adh; e = fmaxf(e, NEG_ATT * e);
        float x = __expf(e);
        ds += x;
        unsigned long long xx = pack2(x, x);
        acc64[0] = ffma2(v0.x, xx, acc64[0]);
        acc64[1] = ffma2(v0.y, xx, acc64[1]);
        acc64[2] = ffma2(v1.x, xx, acc64[2]);
        acc64[3] = ffma2(v1.y, xx, acc64[3]);
    }
    if (i + 2 + half < end) {
        int s = g_esrc[i + 2 + half];
        float a = g_as1[s * 8 + h];
        ulonglong2 v0 = h1p[(size_t)s * 32 + 2 * li];
        ulonglong2 v1 = h1p[(size_t)s * 32 + 2 * li + 1];
        float e = a + adh; e = fmaxf(e, NEG_ATT * e);
        float x = __expf(e);
        ds += x;
        unsigned long long xx = pack2(x, x);
        acc64[0] = ffma2(v0.x, xx, acc64[0]);
        acc64[1] = ffma2(v0.y, xx, acc64[1]);
        acc64[2] = ffma2(v1.x, xx, acc64[2]);
        acc64[3] = ffma2(v1.y, xx, acc64[3]);
    }

    float acc[8];
#pragma unroll
    for (int k = 0; k < 4; k++) {
        float2 p = unpack2(acc64[k]);
        acc[2 * k] = p.x;
        acc[2 * k + 1] = p.y;
    }
#pragma unroll
    for (int k = 0; k < 8; k++) acc[k] += __shfl_xor_sync(0xFFFFFFFFu, acc[k], 16);
    ds += __shfl_xor_sync(0xFFFFFFFFu, ds, 16);

    float inv = 1.f / ds;
    float4 bb0 = ((const float4*)b1)[2 * li];
    float4 bb1 = ((const float4*)b1)[2 * li + 1];
    float o[8];
    o[0] = acc[0] * inv + bb0.x;
    o[1] = acc[1] * inv + bb0.y;
    o[2] = acc[2] * inv + bb0.z;
    o[3] = acc[3] * inv + bb0.w;
    o[4] = acc[4] * inv + bb1.x;
    o[5] = acc[5] * inv + bb1.y;
    o[6] = acc[6] * inv + bb1.z;
    o[7] = acc[7] * inv + bb1.w;
#pragma unroll
    for (int k = 0; k < 8; k++) o[k] = fmaxf(o[k], NEG_ACT * o[k]);

#pragma unroll
    for (int k = 0; k < 8; k++) hbs[wib][8 * li + k] = o[k];
    __syncwarp();

    int c = l & 15;
    const float* hrow = hbs[wib] + half * 64;
    float g2 = 0.f;
#pragma unroll
    for (int k4 = 0; k4 < 16; k4++) {
        int k = half * 64 + k4 * 4;
        float h0 = hrow[k4 * 4 + 0];
        float h1 = hrow[k4 * 4 + 1];
        float h2 = hrow[k4 * 4 + 2];
        float h3 = hrow[k4 * 4 + 3];
        g2 = fmaf(h0, W2s[(k + 0) * 16 + c], g2);
        g2 = fmaf(h1, W2s[(k + 1) * 16 + c], g2);
        g2 = fmaf(h2, W2s[(k + 2) * 16 + c], g2);
        g2 = fmaf(h3, W2s[(k + 3) * 16 + c], g2);
    }
    g2 += __shfl_xor_sync(0xFFFFFFFFu, g2, 16);
    if (half == 0) g_h2[n * 16 + c] = g2;

    float vs = g2 * __ldg(&a2s[c]);
    float vd = g2 * __ldg(&a2d[c]);
#pragma unroll
    for (int off = 8; off; off >>= 1) {
        vs += __shfl_xor_sync(0xFFFFFFFFu, vs, off);
        vd += __shfl_xor_sync(0xFFFFFFFFu, vd, off);
    }
    if (l == 0) { g_as2[n] = vs; g_ad2[n] = vd; }
}

// ---------------- layer-2 gather + final softmax (MLP=4 per half-warp) ----------------
__global__ void __launch_bounds__(256) k_gather2(const float* __restrict__ b2,
                                                 float* __restrict__ out, int N) {
    int warp = blockIdx.x * 8 + (threadIdx.x >> 5);
    if (warp >= N) return;
    int n = warp;
    int l = threadIdx.x & 31;
    int c = l & 15;
    int half = l >> 4;
    int beg = g_rs[n];
    int cnt = g_rs[n + 1] - beg;
    float ad = g_ad2[n];

    float acc = 0.f, ds = 0.f;
    int j = half;
    for (; j + 6 < cnt; j += 8) {
        int s0 = g_esrc[beg + j + 0];
        int s1 = g_esrc[beg + j + 2];
        int s2 = g_esrc[beg + j + 4];
        int s3 = g_esrc[beg + j + 6];
        float e0 = g_as2[s0] + ad; e0 = fmaxf(e0, NEG_ATT * e0);
        float e1 = g_as2[s1] + ad; e1 = fmaxf(e1, NEG_ATT * e1);
        float e2 = g_as2[s2] + ad; e2 = fmaxf(e2, NEG_ATT * e2);
        float e3 = g_as2[s3] + ad; e3 = fmaxf(e3, NEG_ATT * e3);
        float h0 = g_h2[s0 * 16 + c];
        float h1 = g_h2[s1 * 16 + c];
        float h2 = g_h2[s2 * 16 + c];
        float h3 = g_h2[s3 * 16 + c];
        float x0 = __expf(e0), x1 = __expf(e1), x2 = __expf(e2), x3 = __expf(e3);
        ds += (x0 + x1) + (x2 + x3);
        acc = fmaf(h0, x0, acc);
        acc = fmaf(h1, x1, acc);
        acc = fmaf(h2, x2, acc);
        acc = fmaf(h3, x3, acc);
    }
    for (; j < cnt; j += 2) {
        int s = g_esrc[beg + j];
        float e = g_as2[s] + ad;
        e = fmaxf(e, NEG_ATT * e);
        float ex = __expf(e);
        float hv = g_h2[s * 16 + c];
        acc = fmaf(hv, ex, acc);
        ds += ex;
    }
    acc += __shfl_xor_sync(0xFFFFFFFFu, acc, 16);
    ds += __shfl_xor_sync(0xFFFFFFFFu, ds, 16);

    float o = acc / ds + __ldg(&b2[c]);
    float m = o;
#pragma unroll
    for (int off = 8; off; off >>= 1) m = fmaxf(m, __shfl_xor_sync(0xFFFFFFFFu, m, off));
    float ex = __expf(o - m);
    float sm = ex;
#pragma unroll
    for (int off = 8; off; off >>= 1) sm += __shfl_xor_sync(0xFFFFFFFFu, sm, off);
    if (l < 16) out[(size_t)n * 16 + c] = ex / sm;
}

// ---------------- launch ----------------
extern "C" void kernel_launch(void* const* d_in, const int* in_sizes, int n_in,
                              void* d_out, int out_size) {
    const float* x   = (const float*)d_in[0];
    const int*   ei  = (const int*)d_in[1];
    const float* W1  = (const float*)d_in[2];
    const float* a1s = (const float*)d_in[3];
    const float* a1d = (const float*)d_in[4];
    const float* b1  = (const float*)d_in[5];
    const float* W2  = (const float*)d_in[6];
    const float* a2s = (const float*)d_in[7];
    const float* a2d = (const float*)d_in[8];
    const float* b2  = (const float*)d_in[9];
    float* out = (float*)d_out;

    int N = in_sizes[0] / 128;
    int E = in_sizes[1] / 2;
    const int* src = ei;
    const int* dst = ei + E;

    int nbScan = (N + 511) / 512;
    int GB = (N + 127) / 128;

    k_nop<<<1, 32>>>();                                                // 0
    k_fat<<<GB + HIST_B, 256>>>(x, W1, a1s, a1d, dst, N, E, GB);       // 1
    k_csrsc<<<nbScan, 512>>>(src, dst, N, E, nbScan);                  // 2
    k_gather1<<<(N + 7) / 8, 256>>>(b1, W2, a2s, a2d, N);              // 3 (profiled)
    k_gather2<<<(N + 7) / 8, 256>>>(b2, out, N);                       // 4
}

// round 17
// speedup vs baseline: 1.1465x; 1.1465x over previous
#include <cuda_runtime.h>
#include <cuda_bf16.h>
#include <math.h>
#include <stdint.h>

#define MAXN 100000
#define MAXE 1600000
#define MAXET (MAXN + MAXE)

#define NEG_ATT 0.2f
#define NEG_ACT 0.01f

// ---------------- scratch ----------------
__device__ __nv_bfloat16 g_h1b[MAXN * 128];
__device__ float g_as1[MAXN * 8];
__device__ float g_ad1[MAXN * 8];
__device__ float g_h2[MAXN * 16];
__device__ float g_as2[MAXN];
__device__ float g_ad2[MAXN];
__device__ int   g_deg[MAXN];
__device__ int   g_rs[MAXN + 1];
__device__ int   g_cur[MAXN];
__device__ int   g_esrc[MAXET];
__device__ volatile int g_flag[256];
__device__ int g_aggval[256];
__device__ int g_prefval[256];
__device__ int g_done;

__global__ void k_nop() {}

// ---------------- f32x2 helpers ----------------
__device__ __forceinline__ unsigned long long ffma2(unsigned long long a,
                                                    unsigned long long b,
                                                    unsigned long long c) {
    unsigned long long d;
    asm("fma.rn.f32x2 %0, %1, %2, %3;" : "=l"(d) : "l"(a), "l"(b), "l"(c));
    return d;
}
__device__ __forceinline__ unsigned long long pack2(float a, float b) {
    unsigned long long r;
    asm("mov.b64 %0, {%1, %2};" : "=l"(r) : "f"(a), "f"(b));
    return r;
}
__device__ __forceinline__ unsigned long long pack2u(uint32_t a, uint32_t b) {
    unsigned long long r;
    asm("mov.b64 %0, {%1, %2};" : "=l"(r) : "r"(a), "r"(b));
    return r;
}
__device__ __forceinline__ float2 unpack2(unsigned long long v) {
    float2 r;
    asm("mov.b64 {%0, %1}, %2;" : "=f"(r.x), "=f"(r.y) : "l"(v));
    return r;
}

// -------- fat kernel: SGEMM1, warp-tile 32x64 (conflict-free LDS) + alpha1 || hist --------
#define HIST_B 256
__global__ void __launch_bounds__(256, 2) k_fat(const float* __restrict__ x,
                      const float* __restrict__ W,
                      const float* __restrict__ a1s, const float* __restrict__ a1d,
                      const int* __restrict__ dst, int N, int E, int GB) {
    if (blockIdx.x == 0 && threadIdx.x == 0) g_done = 0;
    if (blockIdx.x >= GB) {
        int b = blockIdx.x - GB;
        for (int e = b * 256 + threadIdx.x; e < E; e += 256 * HIST_B)
            atomicAdd(&g_deg[dst[e]], 1);
        return;
    }
    __shared__ float As[16][128];   // k-major: As[k][node]
    __shared__ float Bs[16][128];   // Bs[k][col]
    int t = threadIdx.x;
    int w = t >> 5, l = t & 31;
    int ly = l >> 3, lx = l & 7;
    int nodeB = (w & 3) * 32 + ly * 8;   // 8 nodes
    int colB = (w >> 2) * 64 + lx * 8;   // 8 cols
    int n0 = blockIdx.x * 128;
    const float4* x4 = (const float4*)x;
    const float4* W4 = (const float4*)W;

    unsigned long long acc[8][4];
#pragma unroll
    for (int i = 0; i < 8; i++)
#pragma unroll
        for (int j = 0; j < 4; j++) acc[i][j] = 0ULL;

    for (int kc = 0; kc < 128; kc += 16) {
#pragma unroll
        for (int i = 0; i < 2; i++) {
            int s = t * 2 + i;
            int row = s >> 2, c4 = s & 3;
            float4 v = make_float4(0.f, 0.f, 0.f, 0.f);
            if (n0 + row < N) v = x4[(size_t)(n0 + row) * 32 + (kc >> 2) + c4];
            As[c4 * 4 + 0][row] = v.x;
            As[c4 * 4 + 1][row] = v.y;
            As[c4 * 4 + 2][row] = v.z;
            As[c4 * 4 + 3][row] = v.w;
        }
#pragma unroll
        for (int i = 0; i < 2; i++) {
            int s = t * 2 + i;
            int row = s >> 5, c4 = s & 31;
            ((float4*)Bs[row])[c4] = W4[(size_t)(kc + row) * 32 + c4];
        }
        __syncthreads();
#pragma unroll
        for (int kk = 0; kk < 16; kk++) {
            float4 af0 = *(const float4*)&As[kk][nodeB];
            float4 af1 = *(const float4*)&As[kk][nodeB + 4];
            const unsigned long long* bp = (const unsigned long long*)&Bs[kk][colB];
            unsigned long long b0 = bp[0], b1 = bp[1], b2 = bp[2], b3 = bp[3];
            float a[8] = {af0.x, af0.y, af0.z, af0.w, af1.x, af1.y, af1.z, af1.w};
#pragma unroll
            for (int i = 0; i < 8; i++) {
                unsigned long long aa = pack2(a[i], a[i]);
                acc[i][0] = ffma2(aa, b0, acc[i][0]);
                acc[i][1] = ffma2(aa, b1, acc[i][1]);
                acc[i][2] = ffma2(aa, b2, acc[i][2]);
                acc[i][3] = ffma2(aa, b3, acc[i][3]);
            }
        }
        __syncthreads();
    }

    // epilogue: thread owns nodes nodeB+i, cols colB..colB+7 (within head colB>>4)
    float asv[8], adv[8];
#pragma unroll
    for (int j = 0; j < 8; j++) {
        asv[j] = __ldg(&a1s[colB + j]);
        adv[j] = __ldg(&a1d[colB + j]);
    }
    int hh = colB >> 4;
#pragma unroll
    for (int i = 0; i < 8; i++) {
        int n = n0 + nodeB + i;
        float h[8];
#pragma unroll
        for (int j = 0; j < 4; j++) {
            float2 p = unpack2(acc[i][j]);
            h[2 * j] = p.x;
            h[2 * j + 1] = p.y;
        }
        float vs = 0.f, vd = 0.f;
#pragma unroll
        for (int j = 0; j < 8; j++) {
            vs = fmaf(h[j], asv[j], vs);
            vd = fmaf(h[j], adv[j], vd);
        }
        // lane l and l^1: same node, two col-halves of the same head
        vs += __shfl_xor_sync(0xFFFFFFFFu, vs, 1);
        vd += __shfl_xor_sync(0xFFFFFFFFu, vd, 1);
        if (n < N) {
            uint4 wbv;
            __nv_bfloat162 bv;
            bv = __floats2bfloat162_rn(h[0], h[1]); wbv.x = *(uint32_t*)&bv;
            bv = __floats2bfloat162_rn(h[2], h[3]); wbv.y = *(uint32_t*)&bv;
            bv = __floats2bfloat162_rn(h[4], h[5]); wbv.z = *(uint32_t*)&bv;
            bv = __floats2bfloat162_rn(h[6], h[7]); wbv.w = *(uint32_t*)&bv;
            *(uint4*)(g_h1b + (size_t)n * 128 + colB) = wbv;
            if ((lx & 1) == 0) {
                g_as1[n * 8 + hh] = vs;
                g_ad1[n * 8 + hh] = vd;
            }
        }
    }
}

// ------- CSR offsets (decoupled lookback) + edge scatter, fused via phase barrier -------
__global__ void __launch_bounds__(512) k_csrsc(const int* __restrict__ src,
                                               const int* __restrict__ dst,
                                               int N, int E, int nb) {
    __shared__ int s[512];
    __shared__ int s_excl;
    int t = threadIdx.x;
    int b = blockIdx.x;
    int i = b * 512 + t;
    int v = (i < N) ? g_deg[i] + 1 : 0;
    s[t] = v;
    __syncthreads();
    for (int off = 1; off < 512; off <<= 1) {
        int x = (t >= off) ? s[t - off] : 0;
        __syncthreads();
        s[t] += x;
        __syncthreads();
    }
    int incl = s[t];
    int total = s[511];

    if (t < 32) {
        if (b == 0) {
            if (t == 0) {
                g_prefval[0] = total;
                __threadfence();
                g_flag[0] = 2;
                s_excl = 0;
                if (nb == 1) g_rs[N] = total;
            }
        } else {
            if (t == 0) {
                g_aggval[b] = total;
                __threadfence();
                g_flag[b] = 1;
            }
            __syncwarp();
            int run = 0;
            int hi = b;
            while (true) {
                int p = hi - 32 + t;
                int f = 2, val = 0;
                if (p >= 0) {
                    do { f = g_flag[p]; } while (f == 0);
                    val = (f == 2) ? g_prefval[p] : g_aggval[p];
                }
                unsigned m = __ballot_sync(0xFFFFFFFFu, f == 2);
                if (m) {
                    int lead = 31 - __clz(m);
                    int contrib = (t >= lead) ? val : 0;
                    run += __reduce_add_sync(0xFFFFFFFFu, contrib);
                    break;
                } else {
                    run += __reduce_add_sync(0xFFFFFFFFu, val);
                    hi -= 32;
                }
            }
            if (t == 0) {
                g_prefval[b] = run + total;
                __threadfence();
                g_flag[b] = 2;
                s_excl = run;
                if (b == nb - 1) g_rs[N] = run + total;
            }
        }
    }
    __syncthreads();
    int excl = s_excl + incl - v;
    if (i < N) {
        g_rs[i] = excl;
        g_cur[i] = excl + 1;
        g_esrc[excl] = i;
        g_deg[i] = 0;
    }

    __threadfence();
    __syncthreads();
    if (t == 0) {
        atomicAdd(&g_done, 1);
        while (*(volatile int*)&g_done < nb) { }
    }
    __syncthreads();
    __threadfence();

    if (b == 0 && t < 256) g_flag[t] = 0;
    int gtid = b * 512 + t;
    int nthreads = nb * 512;
    int E4 = E >> 2;
    for (int q = gtid; q < E4; q += nthreads) {
        int4 s4 = *(const int4*)(src + q * 4);
        int4 d4 = *(const int4*)(dst + q * 4);
        int p0 = atomicAdd(&g_cur[d4.x], 1);
        int p1 = atomicAdd(&g_cur[d4.y], 1);
        int p2 = atomicAdd(&g_cur[d4.z], 1);
        int p3 = atomicAdd(&g_cur[d4.w], 1);
        g_esrc[p0] = s4.x;
        g_esrc[p1] = s4.y;
        g_esrc[p2] = s4.z;
        g_esrc[p3] = s4.w;
    }
    if (gtid == 0) {
        for (int e = E4 * 4; e < E; e++) {
            int p = atomicAdd(&g_cur[dst[e]], 1);
            g_esrc[p] = src[e];
        }
    }
}

// ------- layer-1 gather: 2 edges/warp, PRMT + FFMA2 accumulate + fused GEMM2 -------
__device__ __forceinline__ void accum4x2(unsigned long long* acc, uint4 v,
                                         unsigned long long xx) {
    uint32_t l0 = __byte_perm(v.x, 0, 0x1044);
    uint32_t h0 = __byte_perm(v.x, 0, 0x3244);
    uint32_t l1 = __byte_perm(v.y, 0, 0x1044);
    uint32_t h1 = __byte_perm(v.y, 0, 0x3244);
    uint32_t l2 = __byte_perm(v.z, 0, 0x1044);
    uint32_t h2 = __byte_perm(v.z, 0, 0x3244);
    uint32_t l3 = __byte_perm(v.w, 0, 0x1044);
    uint32_t h3 = __byte_perm(v.w, 0, 0x3244);
    acc[0] = ffma2(pack2u(l0, h0), xx, acc[0]);
    acc[1] = ffma2(pack2u(l1, h1), xx, acc[1]);
    acc[2] = ffma2(pack2u(l2, h2), xx, acc[2]);
    acc[3] = ffma2(pack2u(l3, h3), xx, acc[3]);
}

__global__ void __launch_bounds__(256) k_gather1(const float* __restrict__ b1,
                                                 const float* __restrict__ W2,
                                                 const float* __restrict__ a2s,
                                                 const float* __restrict__ a2d,
                                                 int N) {
    __shared__ float W2s[128 * 16];
    __shared__ float hbs[8][132];
    int t = threadIdx.x;
    for (int i = t; i < 2048; i += 256) W2s[i] = W2[i];
    __syncthreads();

    int wib = t >> 5;
    int warp = blockIdx.x * 8 + wib;
    if (warp >= N) return;
    int n = warp;
    int l = t & 31;
    int half = l >> 4;
    int li = l & 15;
    int h = li >> 1;
    int beg = g_rs[n];
    int end = g_rs[n + 1];
    float adh = g_ad1[n * 8 + h];

    const uint4* h1p = (const uint4*)g_h1b;
    unsigned long long acc64[4];
#pragma unroll
    for (int k = 0; k < 4; k++) acc64[k] = 0ULL;
    float ds = 0.f;

    int i = beg;
    int p0 = 0, p1 = 0;
    if (i + 4 <= end) {
        p0 = g_esrc[i + half];
        p1 = g_esrc[i + 2 + half];
    }
    while (i + 4 <= end) {
        int s0 = p0, s1 = p1;
        int inext = i + 4;
        if (inext + 4 <= end) {
            p0 = g_esrc[inext + half];
            p1 = g_esrc[inext + 2 + half];
        }
        float a0 = g_as1[s0 * 8 + h];
        float a1 = g_as1[s1 * 8 + h];
        uint4 v0 = h1p[s0 * 16 + li];
        uint4 v1 = h1p[s1 * 16 + li];
        float e0 = a0 + adh; e0 = fmaxf(e0, NEG_ATT * e0);
        float e1 = a1 + adh; e1 = fmaxf(e1, NEG_ATT * e1);
        float x0 = __expf(e0), x1 = __expf(e1);
        ds += x0 + x1;
        accum4x2(acc64, v0, pack2(x0, x0));
        accum4x2(acc64, v1, pack2(x1, x1));
        i = inext;
    }
    if (i + half < end) {
        int s = g_esrc[i + half];
        float a = g_as1[s * 8 + h];
        uint4 v = h1p[s * 16 + li];
        float e = a + adh; e = fmaxf(e, NEG_ATT * e);
        float x = __expf(e);
        ds += x;
        accum4x2(acc64, v, pack2(x, x));
    }
    if (i + 2 + half < end) {
        int s = g_esrc[i + 2 + half];
        float a = g_as1[s * 8 + h];
        uint4 v = h1p[s * 16 + li];
        float e = a + adh; e = fmaxf(e, NEG_ATT * e);
        float x = __expf(e);
        ds += x;
        accum4x2(acc64, v, pack2(x, x));
    }

    float acc[8];
#pragma unroll
    for (int k = 0; k < 4; k++) {
        float2 p = unpack2(acc64[k]);
        acc[2 * k] = p.x;
        acc[2 * k + 1] = p.y;
    }
#pragma unroll
    for (int k = 0; k < 8; k++) acc[k] += __shfl_xor_sync(0xFFFFFFFFu, acc[k], 16);
    ds += __shfl_xor_sync(0xFFFFFFFFu, ds, 16);

    float inv = 1.f / ds;
    float4 bb0 = ((const float4*)b1)[2 * li];
    float4 bb1 = ((const float4*)b1)[2 * li + 1];
    float o[8];
    o[0] = acc[0] * inv + bb0.x;
    o[1] = acc[1] * inv + bb0.y;
    o[2] = acc[2] * inv + bb0.z;
    o[3] = acc[3] * inv + bb0.w;
    o[4] = acc[4] * inv + bb1.x;
    o[5] = acc[5] * inv + bb1.y;
    o[6] = acc[6] * inv + bb1.z;
    o[7] = acc[7] * inv + bb1.w;
#pragma unroll
    for (int k = 0; k < 8; k++) o[k] = fmaxf(o[k], NEG_ACT * o[k]);

#pragma unroll
    for (int k = 0; k < 8; k++) hbs[wib][8 * li + k] = o[k];
    __syncwarp();

    int c = l & 15;
    const float* hrow = hbs[wib] + half * 64;
    float g2 = 0.f;
#pragma unroll
    for (int k4 = 0; k4 < 16; k4++) {
        int k = half * 64 + k4 * 4;
        float h0 = hrow[k4 * 4 + 0];
        float h1 = hrow[k4 * 4 + 1];
        float h2 = hrow[k4 * 4 + 2];
        float h3 = hrow[k4 * 4 + 3];
        g2 = fmaf(h0, W2s[(k + 0) * 16 + c], g2);
        g2 = fmaf(h1, W2s[(k + 1) * 16 + c], g2);
        g2 = fmaf(h2, W2s[(k + 2) * 16 + c], g2);
        g2 = fmaf(h3, W2s[(k + 3) * 16 + c], g2);
    }
    g2 += __shfl_xor_sync(0xFFFFFFFFu, g2, 16);
    if (half == 0) g_h2[n * 16 + c] = g2;

    float vs = g2 * __ldg(&a2s[c]);
    float vd = g2 * __ldg(&a2d[c]);
#pragma unroll
    for (int off = 8; off; off >>= 1) {
        vs += __shfl_xor_sync(0xFFFFFFFFu, vs, off);
        vd += __shfl_xor_sync(0xFFFFFFFFu, vd, off);
    }
    if (l == 0) { g_as2[n] = vs; g_ad2[n] = vd; }
}

// ---------------- layer-2 gather + final softmax (MLP=4 per half-warp) ----------------
__global__ void __launch_bounds__(256) k_gather2(const float* __restrict__ b2,
                                                 float* __restrict__ out, int N) {
    int warp = blockIdx.x * 8 + (threadIdx.x >> 5);
    if (warp >= N) return;
    int n = warp;
    int l = threadIdx.x & 31;
    int c = l & 15;
    int half = l >> 4;
    int beg = g_rs[n];
    int cnt = g_rs[n + 1] - beg;
    float ad = g_ad2[n];

    float acc = 0.f, ds = 0.f;
    int j = half;
    for (; j + 6 < cnt; j += 8) {
        int s0 = g_esrc[beg + j + 0];
        int s1 = g_esrc[beg + j + 2];
        int s2 = g_esrc[beg + j + 4];
        int s3 = g_esrc[beg + j + 6];
        float e0 = g_as2[s0] + ad; e0 = fmaxf(e0, NEG_ATT * e0);
        float e1 = g_as2[s1] + ad; e1 = fmaxf(e1, NEG_ATT * e1);
        float e2 = g_as2[s2] + ad; e2 = fmaxf(e2, NEG_ATT * e2);
        float e3 = g_as2[s3] + ad; e3 = fmaxf(e3, NEG_ATT * e3);
        float h0 = g_h2[s0 * 16 + c];
        float h1 = g_h2[s1 * 16 + c];
        float h2 = g_h2[s2 * 16 + c];
        float h3 = g_h2[s3 * 16 + c];
        float x0 = __expf(e0), x1 = __expf(e1), x2 = __expf(e2), x3 = __expf(e3);
        ds += (x0 + x1) + (x2 + x3);
        acc = fmaf(h0, x0, acc);
        acc = fmaf(h1, x1, acc);
        acc = fmaf(h2, x2, acc);
        acc = fmaf(h3, x3, acc);
    }
    for (; j < cnt; j += 2) {
        int s = g_esrc[beg + j];
        float e = g_as2[s] + ad;
        e = fmaxf(e, NEG_ATT * e);
        float ex = __expf(e);
        float hv = g_h2[s * 16 + c];
        acc = fmaf(hv, ex, acc);
        ds += ex;
    }
    acc += __shfl_xor_sync(0xFFFFFFFFu, acc, 16);
    ds += __shfl_xor_sync(0xFFFFFFFFu, ds, 16);

    float o = acc / ds + __ldg(&b2[c]);
    float m = o;
#pragma unroll
    for (int off = 8; off; off >>= 1) m = fmaxf(m, __shfl_xor_sync(0xFFFFFFFFu, m, off));
    float ex = __expf(o - m);
    float sm = ex;
#pragma unroll
    for (int off = 8; off; off >>= 1) sm += __shfl_xor_sync(0xFFFFFFFFu, sm, off);
    if (l < 16) out[(size_t)n * 16 + c] = ex / sm;
}

// ---------------- launch ----------------
extern "C" void kernel_launch(void* const* d_in, const int* in_sizes, int n_in,
                              void* d_out, int out_size) {
    const float* x   = (const float*)d_in[0];
    const int*   ei  = (const int*)d_in[1];
    const float* W1  = (const float*)d_in[2];
    const float* a1s = (const float*)d_in[3];
    const float* a1d = (const float*)d_in[4];
    const float* b1  = (const float*)d_in[5];
    const float* W2  = (const float*)d_in[6];
    const float* a2s = (const float*)d_in[7];
    const float* a2d = (const float*)d_in[8];
    const float* b2  = (const float*)d_in[9];
    float* out = (float*)d_out;

    int N = in_sizes[0] / 128;
    int E = in_sizes[1] / 2;
    const int* src = ei;
    const int* dst = ei + E;

    int nbScan = (N + 511) / 512;
    int GB = (N + 127) / 128;

    k_nop<<<1, 32>>>();                                                // 0
    k_fat<<<GB + HIST_B, 256>>>(x, W1, a1s, a1d, dst, N, E, GB);       // 1
    k_csrsc<<<nbScan, 512>>>(src, dst, N, E, nbScan);                  // 2
    k_gather1<<<(N + 7) / 8, 256>>>(b1, W2, a2s, a2d, N);              // 3 (profiled)
    k_gather2<<<(N + 7) / 8, 256>>>(b2, out, N);                       // 4
}